// round 17
// baseline (speedup 1.0000x reference)
#include <cuda_runtime.h>
#include <cuda_fp16.h>
#include <cstdint>
#include <math.h>

#define NMAX 262144
#define GMAX 8192
#define EDIM 118
#define FDIM 128
#define KTAB 512          // intervals per branch (KTAB+1 grid rows)
#define NNODE 4           // nodes per tab block
#define NTABBLK 258
#define NSCANBLK 296

// ---------------- scratch (device globals; no allocation) ----------------
__device__ float   g_y[NMAX];
__device__ float   g_denom[GMAX];
__device__ float   g_ysp[EDIM * 2];                  // softplus(dot/sqrtF) per (e,r)
__device__ uint8_t g_r[GMAX];                        // branch per graph
__device__ float   g_amax;
__device__ float   g_lin[2 * FDIM];                  // F'(0) per branch
__device__ __half  g_tabh[2][KTAB + 1][FDIM];        // residual G(|att|), fp16 rows (256B)

// ---------------- helpers ----------------
__device__ __forceinline__ float s1f(float x) {      // silu(x) - x/2, O(x^2), no cancellation
    return 0.5f * x * tanhf(0.5f * x);
}
// dot of a global row (L1-hot) with an smem vector
__device__ __forceinline__ float dot128g(const float* __restrict__ w,
                                         const float* __restrict__ b) {
    float d0 = 0.f, d1 = 0.f, d2 = 0.f, d3 = 0.f;
#pragma unroll
    for (int k = 0; k < FDIM; k += 8) {
        float4 w0 = __ldg((const float4*)(w + k));
        float4 w1 = __ldg((const float4*)(w + k + 4));
        float4 b0 = *(const float4*)(b + k);
        float4 b1 = *(const float4*)(b + k + 4);
        d0 = fmaf(w0.x, b0.x, d0);
        d1 = fmaf(w0.y, b0.y, d1);
        d2 = fmaf(w0.z, b0.z, d2);
        d3 = fmaf(w0.w, b0.w, d3);
        d0 = fmaf(w1.x, b1.x, d0);
        d1 = fmaf(w1.y, b1.y, d1);
        d2 = fmaf(w1.z, b1.z, d2);
        d3 = fmaf(w1.w, b1.w, d3);
    }
    return (d0 + d1) + (d2 + d3);
}

// ---------------- kernel: parallel prep (zero+sign | amax | y-table) ----------
__global__ void __launch_bounds__(256)
k_prep(const float* __restrict__ Wq, const float* __restrict__ Wk,
       const float* __restrict__ psi, int G) {
    int b = blockIdx.x;
    int t = threadIdx.x;
    if (b < 32) {
        int i = b * 256 + t;
        if (i < G) {
            g_denom[i] = 0.f;
            g_r[i] = (psi[i] < 0.f) ? 1 : 0;
        }
        return;
    }
    if (b == 32) {
        __shared__ float smax[8];
        float m = 0.f;
        const float4* p4 = (const float4*)psi;
        int nv = G / 4;
#pragma unroll 8
        for (int i = t; i < nv; i += 256) {
            float4 v = p4[i];
            m = fmaxf(m, fmaxf(fmaxf(fabsf(v.x), fabsf(v.y)),
                               fmaxf(fabsf(v.z), fabsf(v.w))));
        }
#pragma unroll
        for (int o = 16; o; o >>= 1) m = fmaxf(m, __shfl_xor_sync(0xffffffffu, m, o));
        if ((t & 31) == 0) smax[t >> 5] = m;
        __syncthreads();
        if (t == 0) {
            float mm = 1e-12f;
            for (int i = 0; i < 8; ++i) mm = fmaxf(mm, smax[i]);
            g_amax = mm;
        }
        return;
    }
    // y-table block: element e — dot then softplus
    int e = b - 33;                        // 0..117
    __shared__ float sk[256];
    __shared__ float sp0[4], sp1[4];
    sk[t] = Wk[t];
    __syncthreads();
    float p0 = 0.f, p1 = 0.f;
    if (t < 128) {
        float w = Wq[t * EDIM + e];
        p0 = w * sk[t];
        p1 = w * sk[128 + t];
    }
#pragma unroll
    for (int o = 16; o; o >>= 1) {
        p0 += __shfl_xor_sync(0xffffffffu, p0, o);
        p1 += __shfl_xor_sync(0xffffffffu, p1, o);
    }
    if (t < 128 && (t & 31) == 0) {
        sp0[t >> 5] = p0;
        sp1[t >> 5] = p1;
    }
    __syncthreads();
    if (t == 0) {
        float d0 = (sp0[0] + sp0[1]) + (sp0[2] + sp0[3]);
        float d1 = (sp1[0] + sp1[1]) + (sp1[2] + sp1[3]);
        float q0 = d0 * 0.08838834764831845f;   // 1/sqrt(128)
        float q1 = d1 * 0.08838834764831845f;
        g_ysp[e * 2 + 0] = (q0 > 20.f) ? q0 : log1pf(expf(q0));
        g_ysp[e * 2 + 1] = (q1 > 20.f) ? q1 : log1pf(expf(q1));
    }
}

// ---------------- fused kernel: tab blocks (0..257) + scan blocks (258..553) --
// Tab:  hlin = W1@wv;  h(a) = 0.5a*hlin + W1@s1(a*wv)
//       F(a) - a*F1 = W2 @ [ 0.5*(W1@s1(a*wv)) + s1(h(a)) ];  F1 = wv + 0.25*(W2@hlin)
//       (W rows read straight from global via __ldg; only 5KB smem)
// Scan: flat float4 stream, 4x ILP, table-lookup hit path.
__global__ void __launch_bounds__(512)
k_scantab(const float4* __restrict__ oh4, const int* __restrict__ bs, int nvec,
          const float* __restrict__ Wv, const float* __restrict__ W1,
          const float* __restrict__ W2) {
    __shared__ float swv[FDIM];
    __shared__ float shl[FDIM];
    __shared__ float sSv[NNODE][FDIM];
    __shared__ float sB[NNODE][FDIM];
    int t = threadIdx.x;
    if (blockIdx.x < NTABBLK) {
        // ---------------- tab path (threads 0..127 compute) ----------------
        int b = blockIdx.x;
        int r = (b >= 129) ? 1 : 0;
        int i0 = (b - r * 129) * NNODE;
        float sgn = r ? -1.f : 1.f;
        bool active = (t < 128);
        float wv = 0.f;
        if (active) {
            wv = Wv[r * FDIM + t];
            swv[t] = wv;
        }
        __syncthreads();

        const float* w1row = W1 + t * FDIM;
        const float* w2row = W2 + t * FDIM;
        float amax = g_amax;
        float hlin = 0.f;
        float av[NNODE];
        if (active) {
            hlin = dot128g(w1row, swv);
            shl[t] = hlin;
#pragma unroll
            for (int u = 0; u < NNODE; ++u) {
                int i = i0 + u;
                float mag = (i == 0) ? (amax * (1.f / 8192.f))
                                     : (amax * (float)i * (1.f / KTAB));
                av[u] = sgn * mag;
                sSv[u][t] = s1f(av[u] * wv);
            }
        }
        __syncthreads();
        if (active) {
#pragma unroll
            for (int u = 0; u < NNODE; ++u) {
                if (i0 + u > KTAB) break;
                float tt = dot128g(w1row, sSv[u]);       // W1@s1(a*wv)
                float h = fmaf(0.5f * av[u], hlin, tt);
                sB[u][t] = fmaf(0.5f, tt, s1f(h));
            }
        }
        __syncthreads();
        if (active) {
            if (i0 == 0) {
                float gl = dot128g(w2row, shl);
                g_lin[r * FDIM + t] = fmaf(0.25f, gl, wv);
            }
#pragma unroll
            for (int u = 0; u < NNODE; ++u) {
                int i = i0 + u;
                if (i > KTAB) break;
                float resid = dot128g(w2row, sB[u]);
                g_tabh[r][i][t] = __float2half(resid / (av[u] * av[u]));
            }
        }
    } else {
        // ---------------- scan path ----------------
        int stride = NSCANBLK * 512;
        int start = (blockIdx.x - NTABBLK) * 512 + t;
        for (int base = start; base < nvec; base += 4 * stride) {
            float4 v[4];
            int ii[4];
#pragma unroll
            for (int u = 0; u < 4; ++u) {
                ii[u] = base + u * stride;
                if (ii[u] < nvec) v[u] = __ldcs(oh4 + ii[u]);
                else v[u] = make_float4(0.f, 0.f, 0.f, 0.f);
            }
#pragma unroll
            for (int u = 0; u < 4; ++u) {
                float vv[4] = {v[u].x, v[u].y, v[u].z, v[u].w};
#pragma unroll
                for (int c = 0; c < 4; ++c) {
                    if (vv[c] != 0.f) {
                        unsigned f = 4u * (unsigned)ii[u] + (unsigned)c;
                        unsigned atom = f / 118u;
                        unsigned e = f - atom * 118u;
                        int g = bs[atom];
                        int r = g_r[g];
                        float y = g_ysp[e * 2 + r];
                        g_y[atom] = y;
                        atomicAdd(&g_denom[g], y);
                    }
                }
            }
        }
    }
}

// ---------------- kernel: persistent fused att + lookup + epilogue ------------
__device__ __forceinline__ float att_gather(const float* __restrict__ psi,
                                            const int* __restrict__ bs,
                                            int n0, int nwarps, int lane, int N) {
    float a = 0.f;
    if (lane < 4) {
        int n = n0 + lane * nwarps;
        if (n < N) {
            int g = __ldg(bs + n);
            float p = __ldg(psi + g);
            a = p * g_y[n] / (g_denom[g] + 1e-6f);
        }
    }
    return a;
}

__global__ void __launch_bounds__(256)
k_out(const float* __restrict__ psi, const int* __restrict__ bs,
      float* __restrict__ out, int N) {
    int lane = threadIdx.x & 31;
    int gw = (blockIdx.x * blockDim.x + threadIdx.x) >> 5;
    int nwarps = (gridDim.x * blockDim.x) >> 5;
    int step = 4 * nwarps;
    // F1 for both branches in registers, loaded once per thread
    float4 f1a = ((const float4*)g_lin)[lane];
    float4 f1b = ((const float4*)(g_lin + FDIM))[lane];
    float scale = (float)KTAB / g_amax;

    float a_pref = att_gather(psi, bs, gw, nwarps, lane, N);

    for (int n0 = gw; n0 < N; n0 += step) {
        float att[4];
#pragma unroll
        for (int u = 0; u < 4; ++u)
            att[u] = __shfl_sync(0xffffffffu, a_pref, u);
        // prefetch next chunk's att (loads overlap current processing)
        float a_next = att_gather(psi, bs, n0 + step, nwarps, lane, N);

        uint2 raw[4];
        int nn[4];
#pragma unroll
        for (int u = 0; u < 4; ++u) {
            nn[u] = n0 + u * nwarps;
            int r = (att[u] < 0.f) ? 1 : 0;
            int j = __float2int_rn(fabsf(att[u]) * scale);
            if (j > KTAB) j = KTAB;
            raw[u] = (nn[u] < N) ? __ldg((const uint2*)(&g_tabh[r][j][0]) + lane)
                                 : make_uint2(0u, 0u);
        }
#pragma unroll
        for (int u = 0; u < 4; ++u) {
            if (nn[u] < N) {
                float2 a01 = __half22float2(*(const __half2*)&raw[u].x);
                float2 a23 = __half22float2(*(const __half2*)&raw[u].y);
                float4 f1 = (att[u] < 0.f) ? f1b : f1a;
                float att2 = att[u] * att[u];
                float4 o;
                o.x = fmaf(att[u], f1.x, att2 * a01.x);
                o.y = fmaf(att[u], f1.y, att2 * a01.y);
                o.z = fmaf(att[u], f1.z, att2 * a23.x);
                o.w = fmaf(att[u], f1.w, att2 * a23.y);
                __stcs((float4*)out + (size_t)nn[u] * 32 + lane, o);
            }
        }
        a_pref = a_next;
    }
}

// ---------------- launch ----------------
extern "C" void kernel_launch(void* const* d_in, const int* in_sizes, int n_in,
                              void* d_out, int out_size) {
    const float* oh  = (const float*)d_in[0];
    const float* psi = (const float*)d_in[1];
    const float* Wq  = (const float*)d_in[2];
    const float* Wk  = (const float*)d_in[3];
    const float* Wv  = (const float*)d_in[4];
    const float* W1  = (const float*)d_in[5];
    const float* W2  = (const float*)d_in[6];
    const int*   bs  = (const int*)d_in[7];
    int N = in_sizes[7];
    int G = in_sizes[1];
    float* out = (float*)d_out;

    int nvec = (N * EDIM) / 4;                // N*118 divisible by 4

    k_prep<<<151, 256>>>(Wq, Wk, psi, G);
    k_scantab<<<NTABBLK + NSCANBLK, 512>>>(
        (const float4*)oh, bs, nvec, Wv, W1, W2);
    k_out<<<888, 256>>>(psi, bs, out, N);
}